// round 10
// baseline (speedup 1.0000x reference)
#include <cuda_runtime.h>

#define EPS 1e-8f
#define NTHREADS 256
#define NBLOCKS 1024              // 1024*256*32 = 2^23 float4 = exact bench shape; one wave
#define FIXED_ITERS 32
#define MAX_PARTIALS 4096
#define LN2 0.69314718055994530942

__device__ float g_partials[MAX_PARTIALS];
__device__ unsigned int g_done_count;   // zero-init; reset by last block each launch

__device__ __forceinline__ unsigned int atom_add_release_gpu(unsigned int* p, unsigned int v)
{
    unsigned int old;
    asm volatile("atom.add.release.gpu.u32 %0, [%1], %2;"
                 : "=r"(old) : "l"(p), "r"(v) : "memory");
    return old;
}

__global__ __launch_bounds__(NTHREADS) void cce_fused_kernel(
    const float* __restrict__ input,
    const float* __restrict__ target,
    long long n4,        // number of float4 elements
    float neg_ln2_inv_b, // -ln2 / B
    float* __restrict__ out)
{
    const float4* __restrict__ in4 = (const float4*)input;
    const float4* __restrict__ tg4 = (const float4*)target;

    const long long stride = (long long)NBLOCKS * NTHREADS;
    const long long base = (long long)blockIdx.x * NTHREADS + threadIdx.x;

    float acc0 = 0.0f, acc1 = 0.0f, acc2 = 0.0f, acc3 = 0.0f;

    if (n4 == stride * FIXED_ITERS) {
        // fast path: compile-time trip count, interleaved stride, deep unroll
        // (no min-blocks clamp -> ptxas free to batch loads across iterations)
        #pragma unroll 8
        for (int it = 0; it < FIXED_ITERS; it++) {
            long long i = base + (long long)it * stride;
            float4 a = __ldcs(&in4[i]);
            float4 t = __ldcs(&tg4[i]);
            acc0 += a.x * __log2f(t.x + EPS);
            acc1 += a.y * __log2f(t.y + EPS);
            acc2 += a.z * __log2f(t.z + EPS);
            acc3 += a.w * __log2f(t.w + EPS);
        }
    } else {
        // generic grid-stride fallback (n divisible by 4)
        for (long long i = base; i < n4; i += stride) {
            float4 a = __ldcs(&in4[i]);
            float4 t = __ldcs(&tg4[i]);
            acc0 += a.x * __log2f(t.x + EPS);
            acc1 += a.y * __log2f(t.y + EPS);
            acc2 += a.z * __log2f(t.z + EPS);
            acc3 += a.w * __log2f(t.w + EPS);
        }
    }

    float acc = (acc0 + acc1) + (acc2 + acc3);

    // intra-block reduction (fp32)
    #pragma unroll
    for (int off = 16; off > 0; off >>= 1)
        acc += __shfl_xor_sync(0xFFFFFFFFu, acc, off);

    __shared__ float warp_sums[NTHREADS / 32];
    int lane = threadIdx.x & 31;
    int wid  = threadIdx.x >> 5;
    if (lane == 0) warp_sums[wid] = acc;
    __syncthreads();

    __shared__ bool is_last;
    if (threadIdx.x == 0) {
        float v = warp_sums[0];
        #pragma unroll
        for (int w = 1; w < NTHREADS / 32; w++) v += warp_sums[w];
        g_partials[blockIdx.x] = v;
        // release atomic publishes the partial + bumps the counter in one op
        unsigned int prev = atom_add_release_gpu(&g_done_count, 1u);
        is_last = (prev == (unsigned int)(gridDim.x - 1));
        if (is_last) g_done_count = 0u;   // reset for next graph replay
    }
    __syncthreads();

    if (is_last) {
        // all release-atomics observed -> all partials visible.
        // deterministic final sum in double (fixed read + reduction order).
        double dacc = 0.0;
        for (int i = threadIdx.x; i < NBLOCKS; i += NTHREADS)
            dacc += (double)g_partials[i];

        #pragma unroll
        for (int off = 16; off > 0; off >>= 1)
            dacc += __shfl_xor_sync(0xFFFFFFFFu, dacc, off);

        __shared__ double dwarp_sums[NTHREADS / 32];
        if (lane == 0) dwarp_sums[wid] = dacc;
        __syncthreads();

        if (threadIdx.x == 0) {
            double v = dwarp_sums[0];
            #pragma unroll
            for (int w = 1; w < NTHREADS / 32; w++) v += dwarp_sums[w];
            out[0] = (float)(v * (double)neg_ln2_inv_b);
        }
    }
}

extern "C" void kernel_launch(void* const* d_in, const int* in_sizes, int n_in,
                              void* d_out, int out_size)
{
    const float* input  = (const float*)d_in[0];
    const float* target = (const float*)d_in[1];
    float* out = (float*)d_out;

    long long n = (long long)in_sizes[0];   // B * C, divisible by 4
    long long n4 = n >> 2;
    long long B = n / 128;                  // C = 128 for this problem

    float neg_ln2_inv_b = (float)(-LN2 / (double)B);
    cce_fused_kernel<<<NBLOCKS, NTHREADS>>>(input, target, n4, neg_ln2_inv_b, out);
}

// round 11
// speedup vs baseline: 1.0451x; 1.0451x over previous
#include <cuda_runtime.h>

#define EPS 1e-8f
#define NTHREADS 256
#define NBLOCKS 1024              // 1024*256*32 = 2^23 float4 = exact bench shape; one wave @32regs
#define FIXED_ITERS 32
#define MAX_PARTIALS 4096
#define LN2 0.69314718055994530942

__device__ float g_partials[MAX_PARTIALS];
__device__ unsigned int g_done_count;   // zero-init; reset by last block each launch

__device__ __forceinline__ unsigned int atom_add_release_gpu(unsigned int* p, unsigned int v)
{
    unsigned int old;
    asm volatile("atom.add.release.gpu.u32 %0, [%1], %2;"
                 : "=r"(old) : "l"(p), "r"(v) : "memory");
    return old;
}

__global__ __launch_bounds__(NTHREADS, 8) void cce_fused_kernel(
    const float* __restrict__ input,
    const float* __restrict__ target,
    long long n4,        // number of float4 elements
    float neg_ln2_inv_b, // -ln2 / B
    float* __restrict__ out)
{
    const float4* __restrict__ in4 = (const float4*)input;
    const float4* __restrict__ tg4 = (const float4*)target;

    const long long stride = (long long)NBLOCKS * NTHREADS;
    const long long base = (long long)blockIdx.x * NTHREADS + threadIdx.x;

    float acc0 = 0.0f, acc1 = 0.0f, acc2 = 0.0f, acc3 = 0.0f;

    if (n4 == stride * FIXED_ITERS) {
        // fast path: compile-time trip count, interleaved stride, lg2 instead of ln.
        // launch_bounds(256,8) pins regs<=32 so 1024 blocks = exactly one wave.
        #pragma unroll 4
        for (int it = 0; it < FIXED_ITERS; it++) {
            long long i = base + (long long)it * stride;
            float4 a = __ldcs(&in4[i]);
            float4 t = __ldcs(&tg4[i]);
            acc0 += a.x * __log2f(t.x + EPS);
            acc1 += a.y * __log2f(t.y + EPS);
            acc2 += a.z * __log2f(t.z + EPS);
            acc3 += a.w * __log2f(t.w + EPS);
        }
    } else {
        // generic grid-stride fallback (n divisible by 4)
        for (long long i = base; i < n4; i += stride) {
            float4 a = __ldcs(&in4[i]);
            float4 t = __ldcs(&tg4[i]);
            acc0 += a.x * __log2f(t.x + EPS);
            acc1 += a.y * __log2f(t.y + EPS);
            acc2 += a.z * __log2f(t.z + EPS);
            acc3 += a.w * __log2f(t.w + EPS);
        }
    }

    float acc = (acc0 + acc1) + (acc2 + acc3);

    // intra-block reduction (fp32)
    #pragma unroll
    for (int off = 16; off > 0; off >>= 1)
        acc += __shfl_xor_sync(0xFFFFFFFFu, acc, off);

    __shared__ float warp_sums[NTHREADS / 32];
    int lane = threadIdx.x & 31;
    int wid  = threadIdx.x >> 5;
    if (lane == 0) warp_sums[wid] = acc;
    __syncthreads();

    __shared__ bool is_last;
    if (threadIdx.x == 0) {
        float v = warp_sums[0];
        #pragma unroll
        for (int w = 1; w < NTHREADS / 32; w++) v += warp_sums[w];
        g_partials[blockIdx.x] = v;
        // release atomic publishes the partial + bumps the counter in one op
        unsigned int prev = atom_add_release_gpu(&g_done_count, 1u);
        is_last = (prev == (unsigned int)(gridDim.x - 1));
        if (is_last) g_done_count = 0u;   // reset for next graph replay
    }
    __syncthreads();

    if (is_last) {
        // all release-atomics observed -> all partials visible.
        // deterministic final sum in double (fixed read + reduction order).
        double dacc = 0.0;
        for (int i = threadIdx.x; i < NBLOCKS; i += NTHREADS)
            dacc += (double)g_partials[i];

        #pragma unroll
        for (int off = 16; off > 0; off >>= 1)
            dacc += __shfl_xor_sync(0xFFFFFFFFu, dacc, off);

        __shared__ double dwarp_sums[NTHREADS / 32];
        if (lane == 0) dwarp_sums[wid] = dacc;
        __syncthreads();

        if (threadIdx.x == 0) {
            double v = dwarp_sums[0];
            #pragma unroll
            for (int w = 1; w < NTHREADS / 32; w++) v += dwarp_sums[w];
            out[0] = (float)(v * (double)neg_ln2_inv_b);
        }
    }
}

extern "C" void kernel_launch(void* const* d_in, const int* in_sizes, int n_in,
                              void* d_out, int out_size)
{
    const float* input  = (const float*)d_in[0];
    const float* target = (const float*)d_in[1];
    float* out = (float*)d_out;

    long long n = (long long)in_sizes[0];   // B * C, divisible by 4
    long long n4 = n >> 2;
    long long B = n / 128;                  // C = 128 for this problem

    float neg_ln2_inv_b = (float)(-LN2 / (double)B);
    cce_fused_kernel<<<NBLOCKS, NTHREADS>>>(input, target, n4, neg_ln2_inv_b, out);
}

// round 12
// speedup vs baseline: 1.0510x; 1.0056x over previous
#include <cuda_runtime.h>

#define EPS 1e-8f
#define NTHREADS 512
#define NBLOCKS 512               // 512*512*32 = 2^23 float4 = exact bench shape; one wave @32regs
#define FIXED_ITERS 32
#define MAX_PARTIALS 4096
#define LN2 0.69314718055994530942

__device__ float g_partials[MAX_PARTIALS];
__device__ unsigned int g_done_count;   // zero-init; reset by last block each launch

__device__ __forceinline__ unsigned int atom_add_release_gpu(unsigned int* p, unsigned int v)
{
    unsigned int old;
    asm volatile("atom.add.release.gpu.u32 %0, [%1], %2;"
                 : "=r"(old) : "l"(p), "r"(v) : "memory");
    return old;
}

__global__ __launch_bounds__(NTHREADS, 4) void cce_fused_kernel(
    const float* __restrict__ input,
    const float* __restrict__ target,
    long long n4,        // number of float4 elements
    float neg_ln2_inv_b, // -ln2 / B
    float* __restrict__ out)
{
    const float4* __restrict__ in4 = (const float4*)input;
    const float4* __restrict__ tg4 = (const float4*)target;

    const long long stride = (long long)NBLOCKS * NTHREADS;
    const long long base = (long long)blockIdx.x * NTHREADS + threadIdx.x;

    float acc0 = 0.0f, acc1 = 0.0f, acc2 = 0.0f, acc3 = 0.0f;

    if (n4 == stride * FIXED_ITERS) {
        // fast path: compile-time trip count, interleaved stride, lg2 instead of ln.
        // launch_bounds(512,4) pins regs<=32 so 512 blocks = exactly one wave.
        #pragma unroll 4
        for (int it = 0; it < FIXED_ITERS; it++) {
            long long i = base + (long long)it * stride;
            float4 a = __ldcs(&in4[i]);
            float4 t = __ldcs(&tg4[i]);
            acc0 += a.x * __log2f(t.x + EPS);
            acc1 += a.y * __log2f(t.y + EPS);
            acc2 += a.z * __log2f(t.z + EPS);
            acc3 += a.w * __log2f(t.w + EPS);
        }
    } else {
        // generic grid-stride fallback (n divisible by 4)
        for (long long i = base; i < n4; i += stride) {
            float4 a = __ldcs(&in4[i]);
            float4 t = __ldcs(&tg4[i]);
            acc0 += a.x * __log2f(t.x + EPS);
            acc1 += a.y * __log2f(t.y + EPS);
            acc2 += a.z * __log2f(t.z + EPS);
            acc3 += a.w * __log2f(t.w + EPS);
        }
    }

    float acc = (acc0 + acc1) + (acc2 + acc3);

    // intra-block reduction (fp32)
    #pragma unroll
    for (int off = 16; off > 0; off >>= 1)
        acc += __shfl_xor_sync(0xFFFFFFFFu, acc, off);

    __shared__ float warp_sums[NTHREADS / 32];
    int lane = threadIdx.x & 31;
    int wid  = threadIdx.x >> 5;
    if (lane == 0) warp_sums[wid] = acc;
    __syncthreads();

    __shared__ bool is_last;
    if (threadIdx.x == 0) {
        float v = warp_sums[0];
        #pragma unroll
        for (int w = 1; w < NTHREADS / 32; w++) v += warp_sums[w];
        g_partials[blockIdx.x] = v;
        // release atomic publishes the partial + bumps the counter in one op
        unsigned int prev = atom_add_release_gpu(&g_done_count, 1u);
        is_last = (prev == (unsigned int)(gridDim.x - 1));
        if (is_last) g_done_count = 0u;   // reset for next graph replay
    }
    __syncthreads();

    if (is_last) {
        // all release-atomics observed -> all partials visible.
        // deterministic final sum in double (fixed read + reduction order).
        double dacc = 0.0;
        for (int i = threadIdx.x; i < NBLOCKS; i += NTHREADS)
            dacc += (double)g_partials[i];

        #pragma unroll
        for (int off = 16; off > 0; off >>= 1)
            dacc += __shfl_xor_sync(0xFFFFFFFFu, dacc, off);

        __shared__ double dwarp_sums[NTHREADS / 32];
        if (lane == 0) dwarp_sums[wid] = dacc;
        __syncthreads();

        if (threadIdx.x == 0) {
            double v = dwarp_sums[0];
            #pragma unroll
            for (int w = 1; w < NTHREADS / 32; w++) v += dwarp_sums[w];
            out[0] = (float)(v * (double)neg_ln2_inv_b);
        }
    }
}

extern "C" void kernel_launch(void* const* d_in, const int* in_sizes, int n_in,
                              void* d_out, int out_size)
{
    const float* input  = (const float*)d_in[0];
    const float* target = (const float*)d_in[1];
    float* out = (float*)d_out;

    long long n = (long long)in_sizes[0];   // B * C, divisible by 4
    long long n4 = n >> 2;
    long long B = n / 128;                  // C = 128 for this problem

    float neg_ln2_inv_b = (float)(-LN2 / (double)B);
    cce_fused_kernel<<<NBLOCKS, NTHREADS>>>(input, target, n4, neg_ln2_inv_b, out);
}

// round 13
// speedup vs baseline: 1.0576x; 1.0063x over previous
#include <cuda_runtime.h>

#define EPS 1e-8f
#define NTHREADS 256
#define NBLOCKS 1024              // 1024*256*32 = 2^23 float4 = exact bench shape; one wave @32regs
#define FIXED_ITERS 32
#define MAX_PARTIALS 4096
#define LN2 0.69314718055994530942

__device__ float g_partials[MAX_PARTIALS];
__device__ unsigned int g_done_count;   // zero-init; reset by last block each launch

__device__ __forceinline__ unsigned int atom_add_release_gpu(unsigned int* p, unsigned int v)
{
    unsigned int old;
    asm volatile("atom.add.release.gpu.u32 %0, [%1], %2;"
                 : "=r"(old) : "l"(p), "r"(v) : "memory");
    return old;
}

__global__ __launch_bounds__(NTHREADS, 8) void cce_fused_kernel(
    const float* __restrict__ input,
    const float* __restrict__ target,
    long long n4,        // number of float4 elements
    float neg_ln2_inv_b, // -ln2 / B
    float* __restrict__ out)
{
    const float4* __restrict__ in4 = (const float4*)input;
    const float4* __restrict__ tg4 = (const float4*)target;

    const long long stride = (long long)NBLOCKS * NTHREADS;
    const long long base = (long long)blockIdx.x * NTHREADS + threadIdx.x;

    float acc0 = 0.0f, acc1 = 0.0f, acc2 = 0.0f, acc3 = 0.0f;

    if (n4 == stride * FIXED_ITERS) {
        // fast path: compile-time trip count, interleaved stride, lg2 instead of ln.
        // launch_bounds(256,8) pins regs<=32 so 1024 blocks = exactly one wave.
        #pragma unroll 4
        for (int it = 0; it < FIXED_ITERS; it++) {
            long long i = base + (long long)it * stride;
            float4 a = __ldcs(&in4[i]);
            float4 t = __ldcs(&tg4[i]);
            acc0 += a.x * __log2f(t.x + EPS);
            acc1 += a.y * __log2f(t.y + EPS);
            acc2 += a.z * __log2f(t.z + EPS);
            acc3 += a.w * __log2f(t.w + EPS);
        }
    } else {
        // generic grid-stride fallback (n divisible by 4)
        for (long long i = base; i < n4; i += stride) {
            float4 a = __ldcs(&in4[i]);
            float4 t = __ldcs(&tg4[i]);
            acc0 += a.x * __log2f(t.x + EPS);
            acc1 += a.y * __log2f(t.y + EPS);
            acc2 += a.z * __log2f(t.z + EPS);
            acc3 += a.w * __log2f(t.w + EPS);
        }
    }

    float acc = (acc0 + acc1) + (acc2 + acc3);

    // intra-block reduction (fp32)
    #pragma unroll
    for (int off = 16; off > 0; off >>= 1)
        acc += __shfl_xor_sync(0xFFFFFFFFu, acc, off);

    __shared__ float warp_sums[NTHREADS / 32];
    int lane = threadIdx.x & 31;
    int wid  = threadIdx.x >> 5;
    if (lane == 0) warp_sums[wid] = acc;
    __syncthreads();

    __shared__ bool is_last;
    if (threadIdx.x == 0) {
        float v = warp_sums[0];
        #pragma unroll
        for (int w = 1; w < NTHREADS / 32; w++) v += warp_sums[w];
        g_partials[blockIdx.x] = v;
        // release atomic publishes the partial + bumps the counter in one op
        unsigned int prev = atom_add_release_gpu(&g_done_count, 1u);
        is_last = (prev == (unsigned int)(gridDim.x - 1));
        if (is_last) g_done_count = 0u;   // reset for next graph replay
    }
    __syncthreads();

    if (is_last) {
        // all release-atomics observed -> all partials visible.
        // deterministic final sum in double (fixed read + reduction order).
        double dacc = 0.0;
        for (int i = threadIdx.x; i < NBLOCKS; i += NTHREADS)
            dacc += (double)g_partials[i];

        #pragma unroll
        for (int off = 16; off > 0; off >>= 1)
            dacc += __shfl_xor_sync(0xFFFFFFFFu, dacc, off);

        __shared__ double dwarp_sums[NTHREADS / 32];
        if (lane == 0) dwarp_sums[wid] = dacc;
        __syncthreads();

        if (threadIdx.x == 0) {
            double v = dwarp_sums[0];
            #pragma unroll
            for (int w = 1; w < NTHREADS / 32; w++) v += dwarp_sums[w];
            out[0] = (float)(v * (double)neg_ln2_inv_b);
        }
    }
}

extern "C" void kernel_launch(void* const* d_in, const int* in_sizes, int n_in,
                              void* d_out, int out_size)
{
    const float* input  = (const float*)d_in[0];
    const float* target = (const float*)d_in[1];
    float* out = (float*)d_out;

    long long n = (long long)in_sizes[0];   // B * C, divisible by 4
    long long n4 = n >> 2;
    long long B = n / 128;                  // C = 128 for this problem

    float neg_ln2_inv_b = (float)(-LN2 / (double)B);
    cce_fused_kernel<<<NBLOCKS, NTHREADS>>>(input, target, n4, neg_ln2_inv_b, out);
}